// round 15
// baseline (speedup 1.0000x reference)
#include <cuda_runtime.h>
#include <cuda_fp16.h>
#include <cstdint>

// ---------------------------------------------------------------------------
// ShiftedWindowAttention (Swin window-MSA) — all-fp16 tensor-core pipeline
//   Stage 0: weights -> fp16; fused (mask + rpe-bias) table build
//   Stage 1: qkv GEMM reads x fp32 DIRECTLY (LDG+cvt+STS staging for A,
//            cp.async for W), 3-stage pipeline, head-blocked fp16 output
//   Stage 2: window attention, warp = (window, head)
//   Stage 3: out GEMM (fp16 in via cp.async, fp32 out)
// ---------------------------------------------------------------------------

#define NWIN    4096
#define NTOK    49
#define CDIM    256
#define HEADS_N 8
#define HD      32
#define MROWS   (NWIN * NTOK)    // 200704
#define N3      (3 * CDIM)       // 768
#define QSCALE  0.1767766952966369f

// qkv head-blocked: addr = ((which*8 + h)*MROWS + m)*32 + d
__device__ __half g_qkvh[(size_t)MROWS * N3];
__device__ __half g_ctxh[(size_t)MROWS * CDIM];
__device__ __half g_wqkvh[N3 * CDIM];
__device__ __half g_wouth[CDIM * CDIM];
// fused bias+mask table: [wm 64][h 8][n 64][m 64], pad = -60000
__device__ __align__(16) __half g_bm[64 * 8 * 64 * 64];

// ---------------------------------------------------------------------------
// helpers
// ---------------------------------------------------------------------------
__device__ __forceinline__ uint32_t f2h2(float lo, float hi) {
    uint32_t u;
    asm("cvt.rn.f16x2.f32 %0, %1, %2;" : "=r"(u) : "f"(hi), "f"(lo));
    return u;
}

__device__ __forceinline__ uint32_t s2u(const void* p) {
    return (uint32_t)__cvta_generic_to_shared(p);
}

__device__ __forceinline__ uint4 ldsm4(uint32_t a) {
    uint4 r;
    asm volatile("ldmatrix.sync.aligned.m8n8.x4.shared.b16 {%0,%1,%2,%3}, [%4];"
                 : "=r"(r.x), "=r"(r.y), "=r"(r.z), "=r"(r.w) : "r"(a));
    return r;
}

__device__ __forceinline__ uint4 ldsm4t(uint32_t a) {
    uint4 r;
    asm volatile("ldmatrix.sync.aligned.m8n8.x4.trans.shared.b16 {%0,%1,%2,%3}, [%4];"
                 : "=r"(r.x), "=r"(r.y), "=r"(r.z), "=r"(r.w) : "r"(a));
    return r;
}

__device__ __forceinline__ void cpa16(uint32_t dst, const void* src) {
    asm volatile("cp.async.cg.shared.global [%0], [%1], 16;"
                 :: "r"(dst), "l"(src));
}
__device__ __forceinline__ void cpa_commit() {
    asm volatile("cp.async.commit_group;");
}
__device__ __forceinline__ void cpa_wait1() {
    asm volatile("cp.async.wait_group 1;");
}
__device__ __forceinline__ void cpa_wait0() {
    asm volatile("cp.async.wait_group 0;");
}

__device__ __forceinline__ void mma_f16(float* c, const uint4& a,
                                        unsigned b0, unsigned b1) {
    asm volatile(
        "mma.sync.aligned.m16n8k16.row.col.f32.f16.f16.f32 "
        "{%0,%1,%2,%3}, {%4,%5,%6,%7}, {%8,%9}, {%0,%1,%2,%3};"
        : "+f"(c[0]), "+f"(c[1]), "+f"(c[2]), "+f"(c[3])
        : "r"(a.x), "r"(a.y), "r"(a.z), "r"(a.w), "r"(b0), "r"(b1));
}

// ---------------------------------------------------------------------------
// prepass kernels
// ---------------------------------------------------------------------------
__global__ void __launch_bounds__(256) cvt_w_kernel(
    const float* __restrict__ qkv_w, const float* __restrict__ out_w)
{
    int i = blockIdx.x * 256 + threadIdx.x;
    if (i < (N3 * CDIM) / 4) {
        float4 v = reinterpret_cast<const float4*>(qkv_w)[i];
        reinterpret_cast<uint2*>(g_wqkvh)[i] =
            make_uint2(f2h2(v.x, v.y), f2h2(v.z, v.w));
    } else {
        int j = i - (N3 * CDIM) / 4;
        float4 v = reinterpret_cast<const float4*>(out_w)[j];
        reinterpret_cast<uint2*>(g_wouth)[j] =
            make_uint2(f2h2(v.x, v.y), f2h2(v.z, v.w));
    }
}

// fused bias table: bm[wm][h][n][m] = mask(wm,n,m) + rpe[rel(n,m)][h], pad -6e4
__global__ void __launch_bounds__(256) build_bm_kernel(
    const float* __restrict__ mask, const float* __restrict__ rpe,
    const int* __restrict__ rel_index)
{
    int idx = blockIdx.x * 256 + threadIdx.x;   // 64*8*64*64 total
    int m  = idx & 63;
    int n  = (idx >> 6) & 63;
    int h  = (idx >> 12) & 7;
    int wm = idx >> 15;
    float v = -60000.f;
    if (n < NTOK && m < NTOK) {
        int nm = n * NTOK + m;
        v = mask[wm * NTOK * NTOK + nm] + rpe[rel_index[nm] * HEADS_N + h];
    }
    g_bm[idx] = __float2half(v);
}

// ---------------------------------------------------------------------------
// fp16 GEMM:  Out[m,n] = sum_k A[m,k] * W[n,k] + bias[n]   (K = 256)
// Block 128x128, 8 warps (2m x 4n), warp tile 64x32, chunk = 64 halves,
// THREE-stage pipeline, one barrier per chunk.
// A_F32 variant: A staged from fp32 gmem via coalesced LDG.128 + cvt + STS.64
// (placed AFTER the mma block: data not read until 2 barriers later, so the
// LDG latency overlaps the next iteration's wait/mma).
// ---------------------------------------------------------------------------
#define GEMM_SMEM 98304   // 3 stages x (A 16KB + W 16KB)

// W-only cp.async staging (16 KB -> dstbase+16384)
__device__ __forceinline__ void stage_w_h(
    const __half* __restrict__ Wh, int n0, int c, uint32_t dstbase, int tid)
{
    const int rr   = tid >> 1;
    const int segb = (tid & 1) * 4;
    const char* Ws = reinterpret_cast<const char*>(Wh) +
                     (size_t)(n0 + rr) * 512 + c * 128;
    const uint32_t drow = dstbase + 16384 + rr * 128;
#pragma unroll
    for (int i = 0; i < 4; i++) {
        int seg = segb + i;
        cpa16(drow + ((seg ^ (rr & 7)) << 4), Ws + seg * 16);
    }
}

// A-only cp.async staging (fp16 source, out GEMM path)
__device__ __forceinline__ void stage_a_h(
    const __half* __restrict__ Ah, int m0, int c, uint32_t dstbase, int tid)
{
    const int rr   = tid >> 1;
    const int segb = (tid & 1) * 4;
    const char* As = reinterpret_cast<const char*>(Ah) +
                     (size_t)(m0 + rr) * 512 + c * 128;
    const uint32_t drow = dstbase + rr * 128;
#pragma unroll
    for (int i = 0; i < 4; i++) {
        int seg = segb + i;
        cpa16(drow + ((seg ^ (rr & 7)) << 4), As + seg * 16);
    }
}

// A staging from fp32 source: 8 coalesced LDG.128 + 16 cvt + 8 STS.64
__device__ __forceinline__ void stage_a_f32(
    const float* __restrict__ Af, int m0, int c, char* dst, int tid)
{
#pragma unroll
    for (int i = 0; i < 8; i++) {
        int f   = tid + i * 256;      // float4 index, 0..2047
        int row = f >> 4;             // 0..127
        int fs  = f & 15;             // float4 within row (16 per 64-float chunk)
        float4 v = *reinterpret_cast<const float4*>(
            Af + (size_t)(m0 + row) * 256 + c * 64 + fs * 4);
        uint2 t = make_uint2(f2h2(v.x, v.y), f2h2(v.z, v.w));
        int seg = fs >> 1;            // 16B slot
        *reinterpret_cast<uint2*>(
            dst + row * 128 + ((seg ^ (row & 7)) << 4) + (fs & 1) * 8) = t;
    }
}

template <bool A_F32>
__device__ __forceinline__ void gemm_f16_body(
    const void* __restrict__ Aptr, const __half* __restrict__ Wh,
    const float* __restrict__ bias, void* __restrict__ OutP, int N)
{
    extern __shared__ __align__(16) char sbuf[];

    const int tid  = threadIdx.x;
    const int m0   = blockIdx.y * 128;
    const int n0   = blockIdx.x * 128;
    const int warp = tid >> 5, lane = tid & 31;
    const int qr   = lane >> 2, qc = lane & 3;
    const int wm   = (warp >> 2) * 64;
    const int wn   = (warp & 3) * 32;
    const int g    = lane >> 3, r7 = lane & 7;

    const float* Af = (const float*)Aptr;
    const __half* Ah = (const __half*)Aptr;

    const uint32_t sb = s2u(sbuf);

    uint32_t aA[4], aB[2];
#pragma unroll
    for (int t = 0; t < 4; t++)
        aA[t] = sb + (uint32_t)(wm + 16 * t + (g & 1) * 8 + r7) * 128;
#pragma unroll
    for (int t = 0; t < 2; t++)
        aB[t] = sb + 16384 + (uint32_t)(wn + 16 * t + (g >> 1) * 8 + r7) * 128;

    float acc[4][4][4];
#pragma unroll
    for (int t = 0; t < 4; t++)
#pragma unroll
        for (int nb = 0; nb < 4; nb++)
#pragma unroll
            for (int j = 0; j < 4; j++) acc[t][nb][j] = 0.f;

    // prologue: W chunks 0,1 async; A chunks 0,1 (cvt path stalls here, fine)
    stage_w_h(Wh, n0, 0, sb, tid);
    if (!A_F32) stage_a_h(Ah, m0, 0, sb, tid);
    cpa_commit();
    stage_w_h(Wh, n0, 1, sb + 32768, tid);
    if (!A_F32) stage_a_h(Ah, m0, 1, sb + 32768, tid);
    cpa_commit();
    if (A_F32) {
        stage_a_f32(Af, m0, 0, sbuf, tid);
        stage_a_f32(Af, m0, 1, sbuf + 32768, tid);
    }

#pragma unroll 1
    for (int c = 0; c < 4; c++) {
        cpa_wait1();            // chunk c W (and A if cp.async) landed
        __syncthreads();        // buf (c-1)%3 == (c+2)%3 free; STS visible

        if (c + 2 < 4) {
            stage_w_h(Wh, n0, c + 2, sb + (uint32_t)((c + 2) % 3) * 32768, tid);
            if (!A_F32)
                stage_a_h(Ah, m0, c + 2,
                          sb + (uint32_t)((c + 2) % 3) * 32768, tid);
        }
        cpa_commit();           // uniform group accounting

        const uint32_t soff = (uint32_t)(c % 3) * 32768;
#pragma unroll
        for (int s = 0; s < 4; s++) {
            const uint32_t offA = (uint32_t)(((2 * s + (g >> 1)) ^ r7) << 4) + soff;
            const uint32_t offB = (uint32_t)(((2 * s + (g & 1)) ^ r7) << 4) + soff;
            uint4 a0 = ldsm4(aA[0] + offA);
            uint4 a1 = ldsm4(aA[1] + offA);
            uint4 a2 = ldsm4(aA[2] + offA);
            uint4 a3 = ldsm4(aA[3] + offA);
            uint4 b0 = ldsm4(aB[0] + offB);
            uint4 b1 = ldsm4(aB[1] + offB);
            mma_f16(acc[0][0], a0, b0.x, b0.y);
            mma_f16(acc[0][1], a0, b0.z, b0.w);
            mma_f16(acc[0][2], a0, b1.x, b1.y);
            mma_f16(acc[0][3], a0, b1.z, b1.w);
            mma_f16(acc[1][0], a1, b0.x, b0.y);
            mma_f16(acc[1][1], a1, b0.z, b0.w);
            mma_f16(acc[1][2], a1, b1.x, b1.y);
            mma_f16(acc[1][3], a1, b1.z, b1.w);
            mma_f16(acc[2][0], a2, b0.x, b0.y);
            mma_f16(acc[2][1], a2, b0.z, b0.w);
            mma_f16(acc[2][2], a2, b1.x, b1.y);
            mma_f16(acc[2][3], a2, b1.z, b1.w);
            mma_f16(acc[3][0], a3, b0.x, b0.y);
            mma_f16(acc[3][1], a3, b0.z, b0.w);
            mma_f16(acc[3][2], a3, b1.x, b1.y);
            mma_f16(acc[3][3], a3, b1.z, b1.w);
        }

        // A fp32 staging AFTER mma: read 2 barriers later, LDG latency
        // overlaps the next iteration's wait/mma of other warps.
        if (A_F32 && c + 2 < 4)
            stage_a_f32(Af, m0, c + 2,
                        sbuf + (size_t)((c + 2) % 3) * 32768, tid);
    }

#pragma unroll
    for (int t = 0; t < 4; t++) {
#pragma unroll
        for (int nb = 0; nb < 4; nb++) {
            int r = m0 + wm + t * 16 + qr;
            int cc = n0 + wn + nb * 8 + qc * 2;
            float b0 = bias[cc], b1 = bias[cc + 1];
            if (A_F32) {
                // qkv path: head-blocked fp16 ((which*8+h)*MROWS + r)*32 + d
                int which = cc >> 8, hh = (cc >> 5) & 7, dd = cc & 31;
                float sc = (which == 0) ? QSCALE : 1.f;
                __half* Oh = (__half*)OutP;
                size_t base = (size_t)(which * 8 + hh) * MROWS * 32 + dd;
                *reinterpret_cast<uint32_t*>(&Oh[base + (size_t)r * 32]) =
                    f2h2((acc[t][nb][0] + b0) * sc, (acc[t][nb][1] + b1) * sc);
                *reinterpret_cast<uint32_t*>(&Oh[base + (size_t)(r + 8) * 32]) =
                    f2h2((acc[t][nb][2] + b0) * sc, (acc[t][nb][3] + b1) * sc);
            } else {
                float* Of = (float*)OutP;
                *reinterpret_cast<float2*>(&Of[(size_t)r * N + cc]) =
                    make_float2(acc[t][nb][0] + b0, acc[t][nb][1] + b1);
                *reinterpret_cast<float2*>(&Of[(size_t)(r + 8) * N + cc]) =
                    make_float2(acc[t][nb][2] + b0, acc[t][nb][3] + b1);
            }
        }
    }
}

__global__ void __launch_bounds__(256, 2) qkv_gemm_kernel(
    const float* __restrict__ x, const float* __restrict__ qkv_b)
{
    gemm_f16_body<true>(x, g_wqkvh, qkv_b, g_qkvh, N3);
}

__global__ void __launch_bounds__(256, 2) out_gemm_kernel(
    const float* __restrict__ out_b, float* __restrict__ out)
{
    gemm_f16_body<false>(g_ctxh, g_wouth, out_b, out, CDIM);
}

// ---------------------------------------------------------------------------
// fp16 window attention (unchanged from R11).
// ---------------------------------------------------------------------------
#define WBYTES 12288
#define SMEM_ATTN (8 * WBYTES)    // 98304

__global__ void __launch_bounds__(256, 2) win_attn_kernel()
{
    extern __shared__ __align__(16) char smem[];

    const int w    = blockIdx.x;
    const int tid  = threadIdx.x;
    const int lane = tid & 31;
    const int h    = tid >> 5;        // warp == head
    const int qr   = lane >> 2, qc = lane & 3;
    const int g    = lane >> 3, r7 = lane & 7;

    char* wbuf = smem + h * WBYTES;
    const uint32_t qb = s2u(wbuf);
    const uint32_t kb = qb + 4096;
    const uint32_t vb = qb + 8192;

    // ---- zero pad rows 49..63 of Q, K, V ----
    {
        uint4 z = make_uint4(0, 0, 0, 0);
        for (int i = lane; i < 180; i += 32) {
            int b = i / 60, j = i - b * 60;
            *reinterpret_cast<uint4*>(wbuf + b * 4096 + 3136 + j * 16) = z;
        }
    }

    // ---- coalesced staging of Q, K, V (3136 B contiguous each) ----
    {
        const size_t gm = (size_t)w * NTOK * 32;
        const __half* srcQ = g_qkvh + (size_t)h        * MROWS * 32 + gm;
        const __half* srcK = g_qkvh + (size_t)(8 + h)  * MROWS * 32 + gm;
        const __half* srcV = g_qkvh + (size_t)(16 + h) * MROWS * 32 + gm;
        for (int i = lane; i < 196; i += 32) {
            int row = i >> 2, slot = i & 3;
            uint32_t doff = row * 64 + ((slot ^ ((row >> 1) & 3)) << 4);
            cpa16(qb + doff, srcQ + i * 8);
            cpa16(kb + doff, srcK + i * 8);
            cpa16(vb + doff, srcV + i * 8);
        }
        cpa_commit();
        cpa_wait0();
        __syncwarp();
    }

    const __half* bmh = g_bm + ((size_t)(w & 63) * 8 + h) * 4096;

#pragma unroll 1
    for (int half = 0; half < 2; half++) {
        const int mb = half * 32;

        // ---- init S accumulators from fused bias table (row stride 64) ----
        float acc[2][8][4];
#pragma unroll
        for (int mt = 0; mt < 2; mt++) {
            int r0 = mb + mt * 16 + qr;
#pragma unroll
            for (int nt = 0; nt < 8; nt++) {
                int m0 = nt * 8 + 2 * qc;
                __half2 b0 = *reinterpret_cast<const __half2*>(&bmh[r0 * 64 + m0]);
                __half2 b1 = *reinterpret_cast<const __half2*>(&bmh[(r0 + 8) * 64 + m0]);
                float2 f0 = __half22float2(b0);
                float2 f1 = __half22float2(b1);
                acc[mt][nt][0] = f0.x; acc[mt][nt][1] = f0.y;
                acc[mt][nt][2] = f1.x; acc[mt][nt][3] = f1.y;
            }
        }

        // ---- S = Q K^T + bias ----
#pragma unroll
        for (int s = 0; s < 2; s++) {
            uint4 af[2];
#pragma unroll
            for (int mt = 0; mt < 2; mt++) {
                int row  = mb + mt * 16 + (g & 1) * 8 + r7;
                int slot = 2 * s + (g >> 1);
                af[mt] = ldsm4(qb + row * 64 + ((slot ^ ((row >> 1) & 3)) << 4));
            }
#pragma unroll
            for (int p = 0; p < 4; p++) {
                int row  = p * 16 + (g >> 1) * 8 + r7;
                int slot = 2 * s + (g & 1);
                uint4 bb = ldsm4(kb + row * 64 + ((slot ^ ((row >> 1) & 3)) << 4));
#pragma unroll
                for (int mt = 0; mt < 2; mt++) {
                    mma_f16(acc[mt][2 * p],     af[mt], bb.x, bb.y);
                    mma_f16(acc[mt][2 * p + 1], af[mt], bb.z, bb.w);
                }
            }
        }

        // ---- softmax (rows spread over quad lanes) ----
#pragma unroll
        for (int mt = 0; mt < 2; mt++) {
            float mx0 = -1e30f, mx1 = -1e30f;
#pragma unroll
            for (int nt = 0; nt < 8; nt++) {
                mx0 = fmaxf(mx0, fmaxf(acc[mt][nt][0], acc[mt][nt][1]));
                mx1 = fmaxf(mx1, fmaxf(acc[mt][nt][2], acc[mt][nt][3]));
            }
#pragma unroll
            for (int o = 1; o < 4; o <<= 1) {
                mx0 = fmaxf(mx0, __shfl_xor_sync(0xffffffffu, mx0, o));
                mx1 = fmaxf(mx1, __shfl_xor_sync(0xffffffffu, mx1, o));
            }
            float s0 = 0.f, s1 = 0.f;
#pragma unroll
            for (int nt = 0; nt < 8; nt++) {
                acc[mt][nt][0] = __expf(acc[mt][nt][0] - mx0);
                acc[mt][nt][1] = __expf(acc[mt][nt][1] - mx0);
                acc[mt][nt][2] = __expf(acc[mt][nt][2] - mx1);
                acc[mt][nt][3] = __expf(acc[mt][nt][3] - mx1);
                s0 += acc[mt][nt][0] + acc[mt][nt][1];
                s1 += acc[mt][nt][2] + acc[mt][nt][3];
            }
#pragma unroll
            for (int o = 1; o < 4; o <<= 1) {
                s0 += __shfl_xor_sync(0xffffffffu, s0, o);
                s1 += __shfl_xor_sync(0xffffffffu, s1, o);
            }
            float i0 = 1.f / s0, i1 = 1.f / s1;
#pragma unroll
            for (int nt = 0; nt < 8; nt++) {
                acc[mt][nt][0] *= i0; acc[mt][nt][1] *= i0;
                acc[mt][nt][2] *= i1; acc[mt][nt][3] *= i1;
            }
        }

        // ---- C = P V ----
        float cacc[2][4][4];
#pragma unroll
        for (int mt = 0; mt < 2; mt++)
#pragma unroll
            for (int dt = 0; dt < 4; dt++)
#pragma unroll
                for (int j = 0; j < 4; j++) cacc[mt][dt][j] = 0.f;

#pragma unroll
        for (int j = 0; j < 4; j++) {
            uint4 aP[2];
#pragma unroll
            for (int mt = 0; mt < 2; mt++) {
                aP[mt].x = f2h2(acc[mt][2 * j][0],     acc[mt][2 * j][1]);
                aP[mt].y = f2h2(acc[mt][2 * j][2],     acc[mt][2 * j][3]);
                aP[mt].z = f2h2(acc[mt][2 * j + 1][0], acc[mt][2 * j + 1][1]);
                aP[mt].w = f2h2(acc[mt][2 * j + 1][2], acc[mt][2 * j + 1][3]);
            }
#pragma unroll
            for (int dp = 0; dp < 2; dp++) {
                int row  = 16 * j + (g & 1) * 8 + r7;
                int slot = 2 * dp + (g >> 1);
                uint4 bb = ldsm4t(vb + row * 64 + ((slot ^ ((row >> 1) & 3)) << 4));
#pragma unroll
                for (int mt = 0; mt < 2; mt++) {
                    mma_f16(cacc[mt][2 * dp],     aP[mt], bb.x, bb.y);
                    mma_f16(cacc[mt][2 * dp + 1], aP[mt], bb.z, bb.w);
                }
            }
        }

        // ---- store ctx (fp16, standard (M,256) layout for out GEMM) ----
#pragma unroll
        for (int mt = 0; mt < 2; mt++) {
            int n0 = mb + mt * 16 + qr;
#pragma unroll
            for (int dt = 0; dt < 4; dt++) {
                int col = h * HD + dt * 8 + 2 * qc;
                if (n0 < NTOK)
                    *reinterpret_cast<uint32_t*>(
                        &g_ctxh[((size_t)w * NTOK + n0) * CDIM + col]) =
                        f2h2(cacc[mt][dt][0], cacc[mt][dt][1]);
                if (n0 + 8 < NTOK)
                    *reinterpret_cast<uint32_t*>(
                        &g_ctxh[((size_t)w * NTOK + n0 + 8) * CDIM + col]) =
                        f2h2(cacc[mt][dt][2], cacc[mt][dt][3]);
            }
        }
    }
}

// ---------------------------------------------------------------------------
extern "C" void kernel_launch(void* const* d_in, const int* in_sizes, int n_in,
                              void* d_out, int out_size)
{
    const float* x     = (const float*)d_in[0];
    const float* mask  = (const float*)d_in[1];
    const float* qkv_w = (const float*)d_in[2];
    const float* qkv_b = (const float*)d_in[3];
    const float* rpe   = (const float*)d_in[4];
    const float* out_w = (const float*)d_in[5];
    const float* out_b = (const float*)d_in[6];
    const int*   rel   = (const int*)d_in[7];
    float* out = (float*)d_out;

    cudaFuncSetAttribute(win_attn_kernel,
                         cudaFuncAttributeMaxDynamicSharedMemorySize, SMEM_ATTN);
    cudaFuncSetAttribute(qkv_gemm_kernel,
                         cudaFuncAttributeMaxDynamicSharedMemorySize, GEMM_SMEM);
    cudaFuncSetAttribute(out_gemm_kernel,
                         cudaFuncAttributeMaxDynamicSharedMemorySize, GEMM_SMEM);

    cvt_w_kernel<<<((N3 * CDIM + CDIM * CDIM) / 4) / 256, 256>>>(qkv_w, out_w);
    build_bm_kernel<<<(64 * 8 * 64 * 64) / 256, 256>>>(mask, rpe, rel);

    dim3 g1(N3 / 128, MROWS / 128);   // 6 x 1568
    qkv_gemm_kernel<<<g1, 256, GEMM_SMEM>>>(x, qkv_b);

    win_attn_kernel<<<NWIN, 256, SMEM_ATTN>>>();

    dim3 g3(CDIM / 128, MROWS / 128); // 2 x 1568
    out_gemm_kernel<<<g3, 256, GEMM_SMEM>>>(out_b, out);
}

// round 16
// speedup vs baseline: 1.0499x; 1.0499x over previous
#include <cuda_runtime.h>
#include <cuda_fp16.h>
#include <cstdint>

// ---------------------------------------------------------------------------
// ShiftedWindowAttention (Swin window-MSA) — all-fp16 tensor-core pipeline
//   Stage 0: ONE fused prepass: x->fp16, weights->fp16, bias+mask table
//   Stage 1: qkv GEMM (fp16 in/out, head-blocked output, q pre-scaled),
//            3-stage cp.async pipeline, one barrier per K-chunk  [R11 config]
//   Stage 2: window attention, warp = (window, head)
//   Stage 3: out GEMM (same pipelined body, fp32 out)
// ---------------------------------------------------------------------------

#define NWIN    4096
#define NTOK    49
#define CDIM    256
#define HEADS_N 8
#define HD      32
#define MROWS   (NWIN * NTOK)    // 200704
#define N3      (3 * CDIM)       // 768
#define QSCALE  0.1767766952966369f

// qkv head-blocked: addr = ((which*8 + h)*MROWS + m)*32 + d
__device__ __half g_qkvh[(size_t)MROWS * N3];
__device__ __half g_xh[(size_t)MROWS * CDIM];
__device__ __half g_ctxh[(size_t)MROWS * CDIM];
__device__ __half g_wqkvh[N3 * CDIM];
__device__ __half g_wouth[CDIM * CDIM];
// fused bias+mask table: [wm 64][h 8][n 64][m 64], pad = -60000
__device__ __align__(16) __half g_bm[64 * 8 * 64 * 64];

// prepass job boundaries (blocks of 256 threads)
#define PP_X_BLOCKS  ((MROWS * CDIM / 4) / 256)                      // 50176
#define PP_W_BLOCKS  (((N3 * CDIM + CDIM * CDIM) / 4) / 256)         // 256
#define PP_BM_BLOCKS ((64 * 8 * 64 * 64) / 256)                      // 8192
#define PP_TOTAL     (PP_X_BLOCKS + PP_W_BLOCKS + PP_BM_BLOCKS)

// ---------------------------------------------------------------------------
// helpers
// ---------------------------------------------------------------------------
__device__ __forceinline__ uint32_t f2h2(float lo, float hi) {
    uint32_t u;
    asm("cvt.rn.f16x2.f32 %0, %1, %2;" : "=r"(u) : "f"(hi), "f"(lo));
    return u;
}

__device__ __forceinline__ uint32_t s2u(const void* p) {
    return (uint32_t)__cvta_generic_to_shared(p);
}

__device__ __forceinline__ uint4 ldsm4(uint32_t a) {
    uint4 r;
    asm volatile("ldmatrix.sync.aligned.m8n8.x4.shared.b16 {%0,%1,%2,%3}, [%4];"
                 : "=r"(r.x), "=r"(r.y), "=r"(r.z), "=r"(r.w) : "r"(a));
    return r;
}

__device__ __forceinline__ uint4 ldsm4t(uint32_t a) {
    uint4 r;
    asm volatile("ldmatrix.sync.aligned.m8n8.x4.trans.shared.b16 {%0,%1,%2,%3}, [%4];"
                 : "=r"(r.x), "=r"(r.y), "=r"(r.z), "=r"(r.w) : "r"(a));
    return r;
}

__device__ __forceinline__ void cpa16(uint32_t dst, const void* src) {
    asm volatile("cp.async.cg.shared.global [%0], [%1], 16;"
                 :: "r"(dst), "l"(src));
}
__device__ __forceinline__ void cpa_commit() {
    asm volatile("cp.async.commit_group;");
}
__device__ __forceinline__ void cpa_wait1() {
    asm volatile("cp.async.wait_group 1;");
}
__device__ __forceinline__ void cpa_wait0() {
    asm volatile("cp.async.wait_group 0;");
}

__device__ __forceinline__ void mma_f16(float* c, const uint4& a,
                                        unsigned b0, unsigned b1) {
    asm volatile(
        "mma.sync.aligned.m16n8k16.row.col.f32.f16.f16.f32 "
        "{%0,%1,%2,%3}, {%4,%5,%6,%7}, {%8,%9}, {%0,%1,%2,%3};"
        : "+f"(c[0]), "+f"(c[1]), "+f"(c[2]), "+f"(c[3])
        : "r"(a.x), "r"(a.y), "r"(a.z), "r"(a.w), "r"(b0), "r"(b1));
}

// ---------------------------------------------------------------------------
// fused prepass: x -> fp16 | weights -> fp16 | bias+mask table
// ---------------------------------------------------------------------------
__global__ void __launch_bounds__(256) prepass_kernel(
    const float* __restrict__ x,
    const float* __restrict__ qkv_w, const float* __restrict__ out_w,
    const float* __restrict__ mask, const float* __restrict__ rpe,
    const int* __restrict__ rel_index)
{
    int b = blockIdx.x;
    if (b < PP_X_BLOCKS) {
        int i = b * 256 + threadIdx.x;
        float4 v = reinterpret_cast<const float4*>(x)[i];
        reinterpret_cast<uint2*>(g_xh)[i] =
            make_uint2(f2h2(v.x, v.y), f2h2(v.z, v.w));
    } else if (b < PP_X_BLOCKS + PP_W_BLOCKS) {
        int i = (b - PP_X_BLOCKS) * 256 + threadIdx.x;
        if (i < (N3 * CDIM) / 4) {
            float4 v = reinterpret_cast<const float4*>(qkv_w)[i];
            reinterpret_cast<uint2*>(g_wqkvh)[i] =
                make_uint2(f2h2(v.x, v.y), f2h2(v.z, v.w));
        } else {
            int j = i - (N3 * CDIM) / 4;
            float4 v = reinterpret_cast<const float4*>(out_w)[j];
            reinterpret_cast<uint2*>(g_wouth)[j] =
                make_uint2(f2h2(v.x, v.y), f2h2(v.z, v.w));
        }
    } else {
        int idx = (b - PP_X_BLOCKS - PP_W_BLOCKS) * 256 + threadIdx.x;
        int m  = idx & 63;
        int n  = (idx >> 6) & 63;
        int h  = (idx >> 12) & 7;
        int wm = idx >> 15;
        float v = -60000.f;
        if (n < NTOK && m < NTOK) {
            int nm = n * NTOK + m;
            v = mask[wm * NTOK * NTOK + nm] + rpe[rel_index[nm] * HEADS_N + h];
        }
        g_bm[idx] = __float2half(v);
    }
}

// ---------------------------------------------------------------------------
// fp16 GEMM:  Out[m,n] = sum_k A[m,k] * W[n,k] + bias[n]   (K = 256)
// Block 128x128, 8 warps (2m x 4n), warp tile 64x32, chunk = 64 halves,
// THREE-stage cp.async pipeline, ONE __syncthreads per chunk:
//   iter c: wait_group(1); barrier; stage chunk c+2 -> buf (c+2)%3; commit;
//           mma on buf c%3.         [R11 champion configuration]
// ---------------------------------------------------------------------------
#define GEMM_SMEM 98304   // 3 stages x (A 16KB + W 16KB)

__device__ __forceinline__ void stage_chunk_h(
    const __half* __restrict__ Ah, const __half* __restrict__ Wh,
    int m0, int n0, int c, uint32_t dstbase, int tid)
{
    const int rr   = tid >> 1;
    const int segb = (tid & 1) * 4;
    const char* As = reinterpret_cast<const char*>(Ah) +
                     (size_t)(m0 + rr) * 512 + c * 128;
    const char* Ws = reinterpret_cast<const char*>(Wh) +
                     (size_t)(n0 + rr) * 512 + c * 128;
    const uint32_t drow = dstbase + rr * 128;
#pragma unroll
    for (int i = 0; i < 4; i++) {
        int seg = segb + i;
        uint32_t d = drow + ((seg ^ (rr & 7)) << 4);
        cpa16(d,         As + seg * 16);
        cpa16(d + 16384, Ws + seg * 16);
    }
}

template <bool HEAD_OUT>
__device__ __forceinline__ void gemm_f16_body(
    const __half* __restrict__ Ah, const __half* __restrict__ Wh,
    const float* __restrict__ bias, void* __restrict__ OutP, int N)
{
    extern __shared__ __align__(16) char sbuf[];

    const int tid  = threadIdx.x;
    const int m0   = blockIdx.y * 128;
    const int n0   = blockIdx.x * 128;
    const int warp = tid >> 5, lane = tid & 31;
    const int qr   = lane >> 2, qc = lane & 3;
    const int wm   = (warp >> 2) * 64;
    const int wn   = (warp & 3) * 32;
    const int g    = lane >> 3, r7 = lane & 7;

    const uint32_t sb = s2u(sbuf);

    uint32_t aA[4], aB[2];
#pragma unroll
    for (int t = 0; t < 4; t++)
        aA[t] = sb + (uint32_t)(wm + 16 * t + (g & 1) * 8 + r7) * 128;
#pragma unroll
    for (int t = 0; t < 2; t++)
        aB[t] = sb + 16384 + (uint32_t)(wn + 16 * t + (g >> 1) * 8 + r7) * 128;

    float acc[4][4][4];
#pragma unroll
    for (int t = 0; t < 4; t++)
#pragma unroll
        for (int nb = 0; nb < 4; nb++)
#pragma unroll
            for (int j = 0; j < 4; j++) acc[t][nb][j] = 0.f;

    // prologue: stage chunks 0,1 into buffers 0,1
    stage_chunk_h(Ah, Wh, m0, n0, 0, sb, tid);
    cpa_commit();
    stage_chunk_h(Ah, Wh, m0, n0, 1, sb + 32768, tid);
    cpa_commit();

#pragma unroll 1
    for (int c = 0; c < 4; c++) {
        cpa_wait1();            // chunk c landed
        __syncthreads();        // all warps done with buf (c-1)%3 == (c+2)%3

        if (c + 2 < 4)
            stage_chunk_h(Ah, Wh, m0, n0, c + 2,
                          sb + (uint32_t)((c + 2) % 3) * 32768, tid);
        cpa_commit();           // uniform group accounting

        const uint32_t soff = (uint32_t)(c % 3) * 32768;
#pragma unroll
        for (int s = 0; s < 4; s++) {
            const uint32_t offA = (uint32_t)(((2 * s + (g >> 1)) ^ r7) << 4) + soff;
            const uint32_t offB = (uint32_t)(((2 * s + (g & 1)) ^ r7) << 4) + soff;
            uint4 a0 = ldsm4(aA[0] + offA);
            uint4 a1 = ldsm4(aA[1] + offA);
            uint4 a2 = ldsm4(aA[2] + offA);
            uint4 a3 = ldsm4(aA[3] + offA);
            uint4 b0 = ldsm4(aB[0] + offB);
            uint4 b1 = ldsm4(aB[1] + offB);
            mma_f16(acc[0][0], a0, b0.x, b0.y);
            mma_f16(acc[0][1], a0, b0.z, b0.w);
            mma_f16(acc[0][2], a0, b1.x, b1.y);
            mma_f16(acc[0][3], a0, b1.z, b1.w);
            mma_f16(acc[1][0], a1, b0.x, b0.y);
            mma_f16(acc[1][1], a1, b0.z, b0.w);
            mma_f16(acc[1][2], a1, b1.x, b1.y);
            mma_f16(acc[1][3], a1, b1.z, b1.w);
            mma_f16(acc[2][0], a2, b0.x, b0.y);
            mma_f16(acc[2][1], a2, b0.z, b0.w);
            mma_f16(acc[2][2], a2, b1.x, b1.y);
            mma_f16(acc[2][3], a2, b1.z, b1.w);
            mma_f16(acc[3][0], a3, b0.x, b0.y);
            mma_f16(acc[3][1], a3, b0.z, b0.w);
            mma_f16(acc[3][2], a3, b1.x, b1.y);
            mma_f16(acc[3][3], a3, b1.z, b1.w);
        }
    }

#pragma unroll
    for (int t = 0; t < 4; t++) {
#pragma unroll
        for (int nb = 0; nb < 4; nb++) {
            int r = m0 + wm + t * 16 + qr;
            int cc = n0 + wn + nb * 8 + qc * 2;
            float b0 = bias[cc], b1 = bias[cc + 1];
            if (HEAD_OUT) {
                // head-blocked fp16: ((which*8+h)*MROWS + r)*32 + d
                int which = cc >> 8, hh = (cc >> 5) & 7, dd = cc & 31;
                float sc = (which == 0) ? QSCALE : 1.f;
                __half* Oh = (__half*)OutP;
                size_t base = (size_t)(which * 8 + hh) * MROWS * 32 + dd;
                *reinterpret_cast<uint32_t*>(&Oh[base + (size_t)r * 32]) =
                    f2h2((acc[t][nb][0] + b0) * sc, (acc[t][nb][1] + b1) * sc);
                *reinterpret_cast<uint32_t*>(&Oh[base + (size_t)(r + 8) * 32]) =
                    f2h2((acc[t][nb][2] + b0) * sc, (acc[t][nb][3] + b1) * sc);
            } else {
                float* Of = (float*)OutP;
                *reinterpret_cast<float2*>(&Of[(size_t)r * N + cc]) =
                    make_float2(acc[t][nb][0] + b0, acc[t][nb][1] + b1);
                *reinterpret_cast<float2*>(&Of[(size_t)(r + 8) * N + cc]) =
                    make_float2(acc[t][nb][2] + b0, acc[t][nb][3] + b1);
            }
        }
    }
}

__global__ void __launch_bounds__(256, 2) qkv_gemm_kernel(
    const float* __restrict__ qkv_b)
{
    gemm_f16_body<true>(g_xh, g_wqkvh, qkv_b, g_qkvh, N3);
}

__global__ void __launch_bounds__(256, 2) out_gemm_kernel(
    const float* __restrict__ out_b, float* __restrict__ out)
{
    gemm_f16_body<false>(g_ctxh, g_wouth, out_b, out, CDIM);
}

// ---------------------------------------------------------------------------
// fp16 window attention (unchanged from R11 champion).
// ---------------------------------------------------------------------------
#define WBYTES 12288
#define SMEM_ATTN (8 * WBYTES)    // 98304

__global__ void __launch_bounds__(256, 2) win_attn_kernel()
{
    extern __shared__ __align__(16) char smem[];

    const int w    = blockIdx.x;
    const int tid  = threadIdx.x;
    const int lane = tid & 31;
    const int h    = tid >> 5;        // warp == head
    const int qr   = lane >> 2, qc = lane & 3;
    const int g    = lane >> 3, r7 = lane & 7;

    char* wbuf = smem + h * WBYTES;
    const uint32_t qb = s2u(wbuf);
    const uint32_t kb = qb + 4096;
    const uint32_t vb = qb + 8192;

    // ---- zero pad rows 49..63 of Q, K, V ----
    {
        uint4 z = make_uint4(0, 0, 0, 0);
        for (int i = lane; i < 180; i += 32) {
            int b = i / 60, j = i - b * 60;
            *reinterpret_cast<uint4*>(wbuf + b * 4096 + 3136 + j * 16) = z;
        }
    }

    // ---- coalesced staging of Q, K, V (3136 B contiguous each) ----
    {
        const size_t gm = (size_t)w * NTOK * 32;
        const __half* srcQ = g_qkvh + (size_t)h        * MROWS * 32 + gm;
        const __half* srcK = g_qkvh + (size_t)(8 + h)  * MROWS * 32 + gm;
        const __half* srcV = g_qkvh + (size_t)(16 + h) * MROWS * 32 + gm;
        for (int i = lane; i < 196; i += 32) {
            int row = i >> 2, slot = i & 3;
            uint32_t doff = row * 64 + ((slot ^ ((row >> 1) & 3)) << 4);
            cpa16(qb + doff, srcQ + i * 8);
            cpa16(kb + doff, srcK + i * 8);
            cpa16(vb + doff, srcV + i * 8);
        }
        cpa_commit();
        cpa_wait0();
        __syncwarp();
    }

    const __half* bmh = g_bm + ((size_t)(w & 63) * 8 + h) * 4096;

#pragma unroll 1
    for (int half = 0; half < 2; half++) {
        const int mb = half * 32;

        // ---- init S accumulators from fused bias table (row stride 64) ----
        float acc[2][8][4];
#pragma unroll
        for (int mt = 0; mt < 2; mt++) {
            int r0 = mb + mt * 16 + qr;
#pragma unroll
            for (int nt = 0; nt < 8; nt++) {
                int m0 = nt * 8 + 2 * qc;
                __half2 b0 = *reinterpret_cast<const __half2*>(&bmh[r0 * 64 + m0]);
                __half2 b1 = *reinterpret_cast<const __half2*>(&bmh[(r0 + 8) * 64 + m0]);
                float2 f0 = __half22float2(b0);
                float2 f1 = __half22float2(b1);
                acc[mt][nt][0] = f0.x; acc[mt][nt][1] = f0.y;
                acc[mt][nt][2] = f1.x; acc[mt][nt][3] = f1.y;
            }
        }

        // ---- S = Q K^T + bias ----
#pragma unroll
        for (int s = 0; s < 2; s++) {
            uint4 af[2];
#pragma unroll
            for (int mt = 0; mt < 2; mt++) {
                int row  = mb + mt * 16 + (g & 1) * 8 + r7;
                int slot = 2 * s + (g >> 1);
                af[mt] = ldsm4(qb + row * 64 + ((slot ^ ((row >> 1) & 3)) << 4));
            }
#pragma unroll
            for (int p = 0; p < 4; p++) {
                int row  = p * 16 + (g >> 1) * 8 + r7;
                int slot = 2 * s + (g & 1);
                uint4 bb = ldsm4(kb + row * 64 + ((slot ^ ((row >> 1) & 3)) << 4));
#pragma unroll
                for (int mt = 0; mt < 2; mt++) {
                    mma_f16(acc[mt][2 * p],     af[mt], bb.x, bb.y);
                    mma_f16(acc[mt][2 * p + 1], af[mt], bb.z, bb.w);
                }
            }
        }

        // ---- softmax (rows spread over quad lanes) ----
#pragma unroll
        for (int mt = 0; mt < 2; mt++) {
            float mx0 = -1e30f, mx1 = -1e30f;
#pragma unroll
            for (int nt = 0; nt < 8; nt++) {
                mx0 = fmaxf(mx0, fmaxf(acc[mt][nt][0], acc[mt][nt][1]));
                mx1 = fmaxf(mx1, fmaxf(acc[mt][nt][2], acc[mt][nt][3]));
            }
#pragma unroll
            for (int o = 1; o < 4; o <<= 1) {
                mx0 = fmaxf(mx0, __shfl_xor_sync(0xffffffffu, mx0, o));
                mx1 = fmaxf(mx1, __shfl_xor_sync(0xffffffffu, mx1, o));
            }
            float s0 = 0.f, s1 = 0.f;
#pragma unroll
            for (int nt = 0; nt < 8; nt++) {
                acc[mt][nt][0] = __expf(acc[mt][nt][0] - mx0);
                acc[mt][nt][1] = __expf(acc[mt][nt][1] - mx0);
                acc[mt][nt][2] = __expf(acc[mt][nt][2] - mx1);
                acc[mt][nt][3] = __expf(acc[mt][nt][3] - mx1);
                s0 += acc[mt][nt][0] + acc[mt][nt][1];
                s1 += acc[mt][nt][2] + acc[mt][nt][3];
            }
#pragma unroll
            for (int o = 1; o < 4; o <<= 1) {
                s0 += __shfl_xor_sync(0xffffffffu, s0, o);
                s1 += __shfl_xor_sync(0xffffffffu, s1, o);
            }
            float i0 = 1.f / s0, i1 = 1.f / s1;
#pragma unroll
            for (int nt = 0; nt < 8; nt++) {
                acc[mt][nt][0] *= i0; acc[mt][nt][1] *= i0;
                acc[mt][nt][2] *= i1; acc[mt][nt][3] *= i1;
            }
        }

        // ---- C = P V ----
        float cacc[2][4][4];
#pragma unroll
        for (int mt = 0; mt < 2; mt++)
#pragma unroll
            for (int dt = 0; dt < 4; dt++)
#pragma unroll
                for (int j = 0; j < 4; j++) cacc[mt][dt][j] = 0.f;

#pragma unroll
        for (int j = 0; j < 4; j++) {
            uint4 aP[2];
#pragma unroll
            for (int mt = 0; mt < 2; mt++) {
                aP[mt].x = f2h2(acc[mt][2 * j][0],     acc[mt][2 * j][1]);
                aP[mt].y = f2h2(acc[mt][2 * j][2],     acc[mt][2 * j][3]);
                aP[mt].z = f2h2(acc[mt][2 * j + 1][0], acc[mt][2 * j + 1][1]);
                aP[mt].w = f2h2(acc[mt][2 * j + 1][2], acc[mt][2 * j + 1][3]);
            }
#pragma unroll
            for (int dp = 0; dp < 2; dp++) {
                int row  = 16 * j + (g & 1) * 8 + r7;
                int slot = 2 * dp + (g >> 1);
                uint4 bb = ldsm4t(vb + row * 64 + ((slot ^ ((row >> 1) & 3)) << 4));
#pragma unroll
                for (int mt = 0; mt < 2; mt++) {
                    mma_f16(cacc[mt][2 * dp],     aP[mt], bb.x, bb.y);
                    mma_f16(cacc[mt][2 * dp + 1], aP[mt], bb.z, bb.w);
                }
            }
        }

        // ---- store ctx (fp16, standard (M,256) layout for out GEMM) ----
#pragma unroll
        for (int mt = 0; mt < 2; mt++) {
            int n0 = mb + mt * 16 + qr;
#pragma unroll
            for (int dt = 0; dt < 4; dt++) {
                int col = h * HD + dt * 8 + 2 * qc;
                if (n0 < NTOK)
                    *reinterpret_cast<uint32_t*>(
                        &g_ctxh[((size_t)w * NTOK + n0) * CDIM + col]) =
                        f2h2(cacc[mt][dt][0], cacc[mt][dt][1]);
                if (n0 + 8 < NTOK)
                    *reinterpret_cast<uint32_t*>(
                        &g_ctxh[((size_t)w * NTOK + n0 + 8) * CDIM + col]) =
                        f2h2(cacc[mt][dt][2], cacc[mt][dt][3]);
            }
        }
    }
}

// ---------------------------------------------------------------------------
extern "C" void kernel_launch(void* const* d_in, const int* in_sizes, int n_in,
                              void* d_out, int out_size)
{
    const float* x     = (const float*)d_in[0];
    const float* mask  = (const float*)d_in[1];
    const float* qkv_w = (const float*)d_in[2];
    const float* qkv_b = (const float*)d_in[3];
    const float* rpe   = (const float*)d_in[4];
    const float* out_w = (const float*)d_in[5];
    const float* out_b = (const float*)d_in[6];
    const int*   rel   = (const int*)d_in[7];
    float* out = (float*)d_out;

    cudaFuncSetAttribute(win_attn_kernel,
                         cudaFuncAttributeMaxDynamicSharedMemorySize, SMEM_ATTN);
    cudaFuncSetAttribute(qkv_gemm_kernel,
                         cudaFuncAttributeMaxDynamicSharedMemorySize, GEMM_SMEM);
    cudaFuncSetAttribute(out_gemm_kernel,
                         cudaFuncAttributeMaxDynamicSharedMemorySize, GEMM_SMEM);

    prepass_kernel<<<PP_TOTAL, 256>>>(x, qkv_w, out_w, mask, rpe, rel);

    dim3 g1(N3 / 128, MROWS / 128);   // 6 x 1568
    qkv_gemm_kernel<<<g1, 256, GEMM_SMEM>>>(qkv_b);

    win_attn_kernel<<<NWIN, 256, SMEM_ATTN>>>();

    dim3 g3(CDIM / 128, MROWS / 128); // 2 x 1568
    out_gemm_kernel<<<g3, 256, GEMM_SMEM>>>(out_b, out);
}

// round 17
// speedup vs baseline: 1.0617x; 1.0112x over previous
#include <cuda_runtime.h>
#include <cuda_fp16.h>
#include <cstdint>

// ---------------------------------------------------------------------------
// ShiftedWindowAttention (Swin window-MSA) — all-fp16 tensor-core pipeline
//   Stage 0: ONE fused prepass: x->fp16, weights->fp16, bias+mask table
//   Stage 1: qkv GEMM (fp16 in/out, head-blocked output, q pre-scaled),
//            3-stage cp.async pipeline  [R11/R16 champion config]
//   Stage 2: window attention, warp = (window, head); dead col-tile nt=7
//            (kv cols 56..63) eliminated from mma/softmax — bit-identical
//   Stage 3: out GEMM (same pipelined body, fp32 out)
// ---------------------------------------------------------------------------

#define NWIN    4096
#define NTOK    49
#define CDIM    256
#define HEADS_N 8
#define HD      32
#define MROWS   (NWIN * NTOK)    // 200704
#define N3      (3 * CDIM)       // 768
#define QSCALE  0.1767766952966369f

// qkv head-blocked: addr = ((which*8 + h)*MROWS + m)*32 + d
__device__ __half g_qkvh[(size_t)MROWS * N3];
__device__ __half g_xh[(size_t)MROWS * CDIM];
__device__ __half g_ctxh[(size_t)MROWS * CDIM];
__device__ __half g_wqkvh[N3 * CDIM];
__device__ __half g_wouth[CDIM * CDIM];
// fused bias+mask table: [wm 64][h 8][n 64][m 64], pad = -60000
__device__ __align__(16) __half g_bm[64 * 8 * 64 * 64];

// prepass job boundaries (blocks of 256 threads)
#define PP_X_BLOCKS  ((MROWS * CDIM / 4) / 256)                      // 50176
#define PP_W_BLOCKS  (((N3 * CDIM + CDIM * CDIM) / 4) / 256)         // 256
#define PP_BM_BLOCKS ((64 * 8 * 64 * 64) / 256)                      // 8192
#define PP_TOTAL     (PP_X_BLOCKS + PP_W_BLOCKS + PP_BM_BLOCKS)

// ---------------------------------------------------------------------------
// helpers
// ---------------------------------------------------------------------------
__device__ __forceinline__ uint32_t f2h2(float lo, float hi) {
    uint32_t u;
    asm("cvt.rn.f16x2.f32 %0, %1, %2;" : "=r"(u) : "f"(hi), "f"(lo));
    return u;
}

__device__ __forceinline__ uint32_t s2u(const void* p) {
    return (uint32_t)__cvta_generic_to_shared(p);
}

__device__ __forceinline__ uint4 ldsm4(uint32_t a) {
    uint4 r;
    asm volatile("ldmatrix.sync.aligned.m8n8.x4.shared.b16 {%0,%1,%2,%3}, [%4];"
                 : "=r"(r.x), "=r"(r.y), "=r"(r.z), "=r"(r.w) : "r"(a));
    return r;
}

__device__ __forceinline__ uint4 ldsm4t(uint32_t a) {
    uint4 r;
    asm volatile("ldmatrix.sync.aligned.m8n8.x4.trans.shared.b16 {%0,%1,%2,%3}, [%4];"
                 : "=r"(r.x), "=r"(r.y), "=r"(r.z), "=r"(r.w) : "r"(a));
    return r;
}

__device__ __forceinline__ void cpa16(uint32_t dst, const void* src) {
    asm volatile("cp.async.cg.shared.global [%0], [%1], 16;"
                 :: "r"(dst), "l"(src));
}
__device__ __forceinline__ void cpa_commit() {
    asm volatile("cp.async.commit_group;");
}
__device__ __forceinline__ void cpa_wait1() {
    asm volatile("cp.async.wait_group 1;");
}
__device__ __forceinline__ void cpa_wait0() {
    asm volatile("cp.async.wait_group 0;");
}

__device__ __forceinline__ void mma_f16(float* c, const uint4& a,
                                        unsigned b0, unsigned b1) {
    asm volatile(
        "mma.sync.aligned.m16n8k16.row.col.f32.f16.f16.f32 "
        "{%0,%1,%2,%3}, {%4,%5,%6,%7}, {%8,%9}, {%0,%1,%2,%3};"
        : "+f"(c[0]), "+f"(c[1]), "+f"(c[2]), "+f"(c[3])
        : "r"(a.x), "r"(a.y), "r"(a.z), "r"(a.w), "r"(b0), "r"(b1));
}

// ---------------------------------------------------------------------------
// fused prepass: x -> fp16 | weights -> fp16 | bias+mask table
// ---------------------------------------------------------------------------
__global__ void __launch_bounds__(256) prepass_kernel(
    const float* __restrict__ x,
    const float* __restrict__ qkv_w, const float* __restrict__ out_w,
    const float* __restrict__ mask, const float* __restrict__ rpe,
    const int* __restrict__ rel_index)
{
    int b = blockIdx.x;
    if (b < PP_X_BLOCKS) {
        int i = b * 256 + threadIdx.x;
        float4 v = reinterpret_cast<const float4*>(x)[i];
        reinterpret_cast<uint2*>(g_xh)[i] =
            make_uint2(f2h2(v.x, v.y), f2h2(v.z, v.w));
    } else if (b < PP_X_BLOCKS + PP_W_BLOCKS) {
        int i = (b - PP_X_BLOCKS) * 256 + threadIdx.x;
        if (i < (N3 * CDIM) / 4) {
            float4 v = reinterpret_cast<const float4*>(qkv_w)[i];
            reinterpret_cast<uint2*>(g_wqkvh)[i] =
                make_uint2(f2h2(v.x, v.y), f2h2(v.z, v.w));
        } else {
            int j = i - (N3 * CDIM) / 4;
            float4 v = reinterpret_cast<const float4*>(out_w)[j];
            reinterpret_cast<uint2*>(g_wouth)[j] =
                make_uint2(f2h2(v.x, v.y), f2h2(v.z, v.w));
        }
    } else {
        int idx = (b - PP_X_BLOCKS - PP_W_BLOCKS) * 256 + threadIdx.x;
        int m  = idx & 63;
        int n  = (idx >> 6) & 63;
        int h  = (idx >> 12) & 7;
        int wm = idx >> 15;
        float v = -60000.f;
        if (n < NTOK && m < NTOK) {
            int nm = n * NTOK + m;
            v = mask[wm * NTOK * NTOK + nm] + rpe[rel_index[nm] * HEADS_N + h];
        }
        g_bm[idx] = __float2half(v);
    }
}

// ---------------------------------------------------------------------------
// fp16 GEMM (R11/R16 champion configuration, unchanged)
// ---------------------------------------------------------------------------
#define GEMM_SMEM 98304   // 3 stages x (A 16KB + W 16KB)

__device__ __forceinline__ void stage_chunk_h(
    const __half* __restrict__ Ah, const __half* __restrict__ Wh,
    int m0, int n0, int c, uint32_t dstbase, int tid)
{
    const int rr   = tid >> 1;
    const int segb = (tid & 1) * 4;
    const char* As = reinterpret_cast<const char*>(Ah) +
                     (size_t)(m0 + rr) * 512 + c * 128;
    const char* Ws = reinterpret_cast<const char*>(Wh) +
                     (size_t)(n0 + rr) * 512 + c * 128;
    const uint32_t drow = dstbase + rr * 128;
#pragma unroll
    for (int i = 0; i < 4; i++) {
        int seg = segb + i;
        uint32_t d = drow + ((seg ^ (rr & 7)) << 4);
        cpa16(d,         As + seg * 16);
        cpa16(d + 16384, Ws + seg * 16);
    }
}

template <bool HEAD_OUT>
__device__ __forceinline__ void gemm_f16_body(
    const __half* __restrict__ Ah, const __half* __restrict__ Wh,
    const float* __restrict__ bias, void* __restrict__ OutP, int N)
{
    extern __shared__ __align__(16) char sbuf[];

    const int tid  = threadIdx.x;
    const int m0   = blockIdx.y * 128;
    const int n0   = blockIdx.x * 128;
    const int warp = tid >> 5, lane = tid & 31;
    const int qr   = lane >> 2, qc = lane & 3;
    const int wm   = (warp >> 2) * 64;
    const int wn   = (warp & 3) * 32;
    const int g    = lane >> 3, r7 = lane & 7;

    const uint32_t sb = s2u(sbuf);

    uint32_t aA[4], aB[2];
#pragma unroll
    for (int t = 0; t < 4; t++)
        aA[t] = sb + (uint32_t)(wm + 16 * t + (g & 1) * 8 + r7) * 128;
#pragma unroll
    for (int t = 0; t < 2; t++)
        aB[t] = sb + 16384 + (uint32_t)(wn + 16 * t + (g >> 1) * 8 + r7) * 128;

    float acc[4][4][4];
#pragma unroll
    for (int t = 0; t < 4; t++)
#pragma unroll
        for (int nb = 0; nb < 4; nb++)
#pragma unroll
            for (int j = 0; j < 4; j++) acc[t][nb][j] = 0.f;

    stage_chunk_h(Ah, Wh, m0, n0, 0, sb, tid);
    cpa_commit();
    stage_chunk_h(Ah, Wh, m0, n0, 1, sb + 32768, tid);
    cpa_commit();

#pragma unroll 1
    for (int c = 0; c < 4; c++) {
        cpa_wait1();
        __syncthreads();

        if (c + 2 < 4)
            stage_chunk_h(Ah, Wh, m0, n0, c + 2,
                          sb + (uint32_t)((c + 2) % 3) * 32768, tid);
        cpa_commit();

        const uint32_t soff = (uint32_t)(c % 3) * 32768;
#pragma unroll
        for (int s = 0; s < 4; s++) {
            const uint32_t offA = (uint32_t)(((2 * s + (g >> 1)) ^ r7) << 4) + soff;
            const uint32_t offB = (uint32_t)(((2 * s + (g & 1)) ^ r7) << 4) + soff;
            uint4 a0 = ldsm4(aA[0] + offA);
            uint4 a1 = ldsm4(aA[1] + offA);
            uint4 a2 = ldsm4(aA[2] + offA);
            uint4 a3 = ldsm4(aA[3] + offA);
            uint4 b0 = ldsm4(aB[0] + offB);
            uint4 b1 = ldsm4(aB[1] + offB);
            mma_f16(acc[0][0], a0, b0.x, b0.y);
            mma_f16(acc[0][1], a0, b0.z, b0.w);
            mma_f16(acc[0][2], a0, b1.x, b1.y);
            mma_f16(acc[0][3], a0, b1.z, b1.w);
            mma_f16(acc[1][0], a1, b0.x, b0.y);
            mma_f16(acc[1][1], a1, b0.z, b0.w);
            mma_f16(acc[1][2], a1, b1.x, b1.y);
            mma_f16(acc[1][3], a1, b1.z, b1.w);
            mma_f16(acc[2][0], a2, b0.x, b0.y);
            mma_f16(acc[2][1], a2, b0.z, b0.w);
            mma_f16(acc[2][2], a2, b1.x, b1.y);
            mma_f16(acc[2][3], a2, b1.z, b1.w);
            mma_f16(acc[3][0], a3, b0.x, b0.y);
            mma_f16(acc[3][1], a3, b0.z, b0.w);
            mma_f16(acc[3][2], a3, b1.x, b1.y);
            mma_f16(acc[3][3], a3, b1.z, b1.w);
        }
    }

#pragma unroll
    for (int t = 0; t < 4; t++) {
#pragma unroll
        for (int nb = 0; nb < 4; nb++) {
            int r = m0 + wm + t * 16 + qr;
            int cc = n0 + wn + nb * 8 + qc * 2;
            float b0 = bias[cc], b1 = bias[cc + 1];
            if (HEAD_OUT) {
                int which = cc >> 8, hh = (cc >> 5) & 7, dd = cc & 31;
                float sc = (which == 0) ? QSCALE : 1.f;
                __half* Oh = (__half*)OutP;
                size_t base = (size_t)(which * 8 + hh) * MROWS * 32 + dd;
                *reinterpret_cast<uint32_t*>(&Oh[base + (size_t)r * 32]) =
                    f2h2((acc[t][nb][0] + b0) * sc, (acc[t][nb][1] + b1) * sc);
                *reinterpret_cast<uint32_t*>(&Oh[base + (size_t)(r + 8) * 32]) =
                    f2h2((acc[t][nb][2] + b0) * sc, (acc[t][nb][3] + b1) * sc);
            } else {
                float* Of = (float*)OutP;
                *reinterpret_cast<float2*>(&Of[(size_t)r * N + cc]) =
                    make_float2(acc[t][nb][0] + b0, acc[t][nb][1] + b1);
                *reinterpret_cast<float2*>(&Of[(size_t)(r + 8) * N + cc]) =
                    make_float2(acc[t][nb][2] + b0, acc[t][nb][3] + b1);
            }
        }
    }
}

__global__ void __launch_bounds__(256, 2) qkv_gemm_kernel(
    const float* __restrict__ qkv_b)
{
    gemm_f16_body<true>(g_xh, g_wqkvh, qkv_b, g_qkvh, N3);
}

__global__ void __launch_bounds__(256, 2) out_gemm_kernel(
    const float* __restrict__ out_b, float* __restrict__ out)
{
    gemm_f16_body<false>(g_ctxh, g_wouth, out_b, out, CDIM);
}

// ---------------------------------------------------------------------------
// fp16 window attention. nt=7 (kv cols 56..63) is provably dead: K rows are
// zero-padded and bias is -60000, so exp underflows to exactly 0 for every
// valid row. acc[.][7] is kept at 0 (feeds PV j=3 as exact-zero P), and the
// S-mma / bias-init / softmax loops skip it. Bit-identical outputs.
// ---------------------------------------------------------------------------
#define WBYTES 12288
#define SMEM_ATTN (8 * WBYTES)    // 98304

__global__ void __launch_bounds__(256, 2) win_attn_kernel()
{
    extern __shared__ __align__(16) char smem[];

    const int w    = blockIdx.x;
    const int tid  = threadIdx.x;
    const int lane = tid & 31;
    const int h    = tid >> 5;        // warp == head
    const int qr   = lane >> 2, qc = lane & 3;
    const int g    = lane >> 3, r7 = lane & 7;

    char* wbuf = smem + h * WBYTES;
    const uint32_t qb = s2u(wbuf);
    const uint32_t kb = qb + 4096;
    const uint32_t vb = qb + 8192;

    // ---- zero pad rows 49..63 of Q, K, V ----
    {
        uint4 z = make_uint4(0, 0, 0, 0);
        for (int i = lane; i < 180; i += 32) {
            int b = i / 60, j = i - b * 60;
            *reinterpret_cast<uint4*>(wbuf + b * 4096 + 3136 + j * 16) = z;
        }
    }

    // ---- coalesced staging of Q, K, V (3136 B contiguous each) ----
    {
        const size_t gm = (size_t)w * NTOK * 32;
        const __half* srcQ = g_qkvh + (size_t)h        * MROWS * 32 + gm;
        const __half* srcK = g_qkvh + (size_t)(8 + h)  * MROWS * 32 + gm;
        const __half* srcV = g_qkvh + (size_t)(16 + h) * MROWS * 32 + gm;
        for (int i = lane; i < 196; i += 32) {
            int row = i >> 2, slot = i & 3;
            uint32_t doff = row * 64 + ((slot ^ ((row >> 1) & 3)) << 4);
            cpa16(qb + doff, srcQ + i * 8);
            cpa16(kb + doff, srcK + i * 8);
            cpa16(vb + doff, srcV + i * 8);
        }
        cpa_commit();
        cpa_wait0();
        __syncwarp();
    }

    const __half* bmh = g_bm + ((size_t)(w & 63) * 8 + h) * 4096;

#pragma unroll 1
    for (int half = 0; half < 2; half++) {
        const int mb = half * 32;

        // ---- init S accumulators from fused bias table; nt=7 stays 0 ----
        float acc[2][8][4];
#pragma unroll
        for (int mt = 0; mt < 2; mt++) {
            int r0 = mb + mt * 16 + qr;
#pragma unroll
            for (int nt = 0; nt < 7; nt++) {
                int m0 = nt * 8 + 2 * qc;
                __half2 b0 = *reinterpret_cast<const __half2*>(&bmh[r0 * 64 + m0]);
                __half2 b1 = *reinterpret_cast<const __half2*>(&bmh[(r0 + 8) * 64 + m0]);
                float2 f0 = __half22float2(b0);
                float2 f1 = __half22float2(b1);
                acc[mt][nt][0] = f0.x; acc[mt][nt][1] = f0.y;
                acc[mt][nt][2] = f1.x; acc[mt][nt][3] = f1.y;
            }
            acc[mt][7][0] = 0.f; acc[mt][7][1] = 0.f;
            acc[mt][7][2] = 0.f; acc[mt][7][3] = 0.f;
        }

        // ---- S = Q K^T + bias (nt=7 skipped) ----
#pragma unroll
        for (int s = 0; s < 2; s++) {
            uint4 af[2];
#pragma unroll
            for (int mt = 0; mt < 2; mt++) {
                int row  = mb + mt * 16 + (g & 1) * 8 + r7;
                int slot = 2 * s + (g >> 1);
                af[mt] = ldsm4(qb + row * 64 + ((slot ^ ((row >> 1) & 3)) << 4));
            }
#pragma unroll
            for (int p = 0; p < 4; p++) {
                int row  = p * 16 + (g >> 1) * 8 + r7;
                int slot = 2 * s + (g & 1);
                uint4 bb = ldsm4(kb + row * 64 + ((slot ^ ((row >> 1) & 3)) << 4));
#pragma unroll
                for (int mt = 0; mt < 2; mt++) {
                    mma_f16(acc[mt][2 * p], af[mt], bb.x, bb.y);
                    if (p < 3)
                        mma_f16(acc[mt][2 * p + 1], af[mt], bb.z, bb.w);
                }
            }
        }

        // ---- softmax over nt<7 (cols 56..63 are exact zeros) ----
#pragma unroll
        for (int mt = 0; mt < 2; mt++) {
            float mx0 = -1e30f, mx1 = -1e30f;
#pragma unroll
            for (int nt = 0; nt < 7; nt++) {
                mx0 = fmaxf(mx0, fmaxf(acc[mt][nt][0], acc[mt][nt][1]));
                mx1 = fmaxf(mx1, fmaxf(acc[mt][nt][2], acc[mt][nt][3]));
            }
#pragma unroll
            for (int o = 1; o < 4; o <<= 1) {
                mx0 = fmaxf(mx0, __shfl_xor_sync(0xffffffffu, mx0, o));
                mx1 = fmaxf(mx1, __shfl_xor_sync(0xffffffffu, mx1, o));
            }
            float s0 = 0.f, s1 = 0.f;
#pragma unroll
            for (int nt = 0; nt < 7; nt++) {
                acc[mt][nt][0] = __expf(acc[mt][nt][0] - mx0);
                acc[mt][nt][1] = __expf(acc[mt][nt][1] - mx0);
                acc[mt][nt][2] = __expf(acc[mt][nt][2] - mx1);
                acc[mt][nt][3] = __expf(acc[mt][nt][3] - mx1);
                s0 += acc[mt][nt][0] + acc[mt][nt][1];
                s1 += acc[mt][nt][2] + acc[mt][nt][3];
            }
#pragma unroll
            for (int o = 1; o < 4; o <<= 1) {
                s0 += __shfl_xor_sync(0xffffffffu, s0, o);
                s1 += __shfl_xor_sync(0xffffffffu, s1, o);
            }
            float i0 = 1.f / s0, i1 = 1.f / s1;
#pragma unroll
            for (int nt = 0; nt < 7; nt++) {
                acc[mt][nt][0] *= i0; acc[mt][nt][1] *= i0;
                acc[mt][nt][2] *= i1; acc[mt][nt][3] *= i1;
            }
        }

        // ---- C = P V (acc[.][7] == 0 feeds j=3 exactly as before) ----
        float cacc[2][4][4];
#pragma unroll
        for (int mt = 0; mt < 2; mt++)
#pragma unroll
            for (int dt = 0; dt < 4; dt++)
#pragma unroll
                for (int j = 0; j < 4; j++) cacc[mt][dt][j] = 0.f;

#pragma unroll
        for (int j = 0; j < 4; j++) {
            uint4 aP[2];
#pragma unroll
            for (int mt = 0; mt < 2; mt++) {
                aP[mt].x = f2h2(acc[mt][2 * j][0],     acc[mt][2 * j][1]);
                aP[mt].y = f2h2(acc[mt][2 * j][2],     acc[mt][2 * j][3]);
                aP[mt].z = f2h2(acc[mt][2 * j + 1][0], acc[mt][2 * j + 1][1]);
                aP[mt].w = f2h2(acc[mt][2 * j + 1][2], acc[mt][2 * j + 1][3]);
            }
#pragma unroll
            for (int dp = 0; dp < 2; dp++) {
                int row  = 16 * j + (g & 1) * 8 + r7;
                int slot = 2 * dp + (g >> 1);
                uint4 bb = ldsm4t(vb + row * 64 + ((slot ^ ((row >> 1) & 3)) << 4));
#pragma unroll
                for (int mt = 0; mt < 2; mt++) {
                    mma_f16(cacc[mt][2 * dp],     aP[mt], bb.x, bb.y);
                    mma_f16(cacc[mt][2 * dp + 1], aP[mt], bb.z, bb.w);
                }
            }
        }

        // ---- store ctx (fp16, standard (M,256) layout for out GEMM) ----
#pragma unroll
        for (int mt = 0; mt < 2; mt++) {
            int n0 = mb + mt * 16 + qr;
#pragma unroll
            for (int dt = 0; dt < 4; dt++) {
                int col = h * HD + dt * 8 + 2 * qc;
                if (n0 < NTOK)
                    *reinterpret_cast<uint32_t*>(
                        &g_ctxh[((size_t)w * NTOK + n0) * CDIM + col]) =
                        f2h2(cacc[mt][dt][0], cacc[mt][dt][1]);
                if (n0 + 8 < NTOK)
                    *reinterpret_cast<uint32_t*>(
                        &g_ctxh[((size_t)w * NTOK + n0 + 8) * CDIM + col]) =
                        f2h2(cacc[mt][dt][2], cacc[mt][dt][3]);
            }
        }
    }
}

// ---------------------------------------------------------------------------
extern "C" void kernel_launch(void* const* d_in, const int* in_sizes, int n_in,
                              void* d_out, int out_size)
{
    const float* x     = (const float*)d_in[0];
    const float* mask  = (const float*)d_in[1];
    const float* qkv_w = (const float*)d_in[2];
    const float* qkv_b = (const float*)d_in[3];
    const float* rpe   = (const float*)d_in[4];
    const float* out_w = (const float*)d_in[5];
    const float* out_b = (const float*)d_in[6];
    const int*   rel   = (const int*)d_in[7];
    float* out = (float*)d_out;

    cudaFuncSetAttribute(win_attn_kernel,
                         cudaFuncAttributeMaxDynamicSharedMemorySize, SMEM_ATTN);
    cudaFuncSetAttribute(qkv_gemm_kernel,
                         cudaFuncAttributeMaxDynamicSharedMemorySize, GEMM_SMEM);
    cudaFuncSetAttribute(out_gemm_kernel,
                         cudaFuncAttributeMaxDynamicSharedMemorySize, GEMM_SMEM);

    prepass_kernel<<<PP_TOTAL, 256>>>(x, qkv_w, out_w, mask, rpe, rel);

    dim3 g1(N3 / 128, MROWS / 128);   // 6 x 1568
    qkv_gemm_kernel<<<g1, 256, GEMM_SMEM>>>(qkv_b);

    win_attn_kernel<<<NWIN, 256, SMEM_ATTN>>>();

    dim3 g3(CDIM / 128, MROWS / 128); // 2 x 1568
    out_gemm_kernel<<<g3, 256, GEMM_SMEM>>>(out_b, out);
}